// round 6
// baseline (speedup 1.0000x reference)
#include <cuda_runtime.h>
#include <cuda_fp16.h>
#include <cstdint>
#include <cstddef>

// ---------------- problem constants ----------------
#define M_TOT   8192          // B*S
#define N_TOT   4096          // D_OUT
#define K_TOT   4096          // D_IN
#define RANK    16
#define KPAD    4160          // 4096 + 16 lora + 48 pad = 65 * 64
#define NCHUNK  65            // KPAD / 64
#define CTA_M   128
#define CTA_N   256
#define NSTAGE  3

// scratch (device globals: allocation-free scratch)
__device__ __half g_xh[(size_t)M_TOT * KPAD];   // x (fp16) + lora/pad cols
__device__ __half g_wh[(size_t)N_TOT * KPAD];   // w = q*scale (fp16) + loraB/pad cols

// ---------------- helpers ----------------
__device__ __forceinline__ uint32_t smem_u32(const void* p) {
    uint32_t a;
    asm("{ .reg .u64 t; cvta.to.shared.u64 t, %1; cvt.u32.u64 %0, t; }" : "=r"(a) : "l"(p));
    return a;
}
__device__ __forceinline__ void cp16(uint32_t smem_dst, const void* gmem_src) {
    asm volatile("cp.async.cg.shared.global [%0], [%1], 16;" :: "r"(smem_dst), "l"(gmem_src) : "memory");
}
__device__ __forceinline__ uint32_t sw128(uint32_t off) { return off ^ ((off >> 3) & 0x70); }

#define LDMX4(r, addr) \
    asm volatile("ldmatrix.sync.aligned.m8n8.x4.shared.b16 {%0,%1,%2,%3}, [%4];" \
        : "=r"((r)[0]), "=r"((r)[1]), "=r"((r)[2]), "=r"((r)[3]) : "r"(addr))

#define MMA16816(c, a, b) \
    asm volatile("mma.sync.aligned.m16n8k16.row.col.f32.f16.f16.f32 " \
        "{%0,%1,%2,%3}, {%4,%5,%6,%7}, {%8,%9}, {%0,%1,%2,%3};" \
        : "+f"((c)[0]), "+f"((c)[1]), "+f"((c)[2]), "+f"((c)[3]) \
        : "r"((a)[0]), "r"((a)[1]), "r"((a)[2]), "r"((a)[3]), "r"((b)[0]), "r"((b)[1]))

__device__ __forceinline__ uint32_t h2u(__half2 h) { return *(uint32_t*)&h; }

// ---------------- pre-pass kernels ----------------

// x fp32 -> g_xh fp16 for the 512 main chunks per row (no div, grid-stride)
__global__ void k_convert_x(const float* __restrict__ x) {
    const size_t total = (size_t)M_TOT * 512;
    const size_t stride = (size_t)gridDim.x * blockDim.x;
    for (size_t id = (size_t)blockIdx.x * blockDim.x + threadIdx.x; id < total; id += stride) {
        int m = (int)(id >> 9), c = (int)(id & 511);
        const float4* p = (const float4*)(x + ((size_t)m << 12)) + (c << 1);
        float4 a = p[0], b = p[1];
        uint4 o;
        o.x = h2u(__floats2half2_rn(a.x, a.y));
        o.y = h2u(__floats2half2_rn(a.z, a.w));
        o.z = h2u(__floats2half2_rn(b.x, b.y));
        o.w = h2u(__floats2half2_rn(b.z, b.w));
        *(uint4*)(g_xh + (size_t)m * KPAD + ((size_t)c << 3)) = o;
    }
}

// zero pad cols [4112, 4160) of g_xh (lora cols 4096..4111 written by k_xa)
__global__ void k_pad_x() {
    int id = blockIdx.x * blockDim.x + threadIdx.x;   // 8192*8
    int m = id >> 3, c = id & 7;
    if (c >= 6) return;
    uint4 z = {0, 0, 0, 0};
    *(uint4*)(g_xh + (size_t)m * KPAD + 4112 + (c << 3)) = z;
}

// qweight int32 -> g_wh fp16 (q * scale) for the 512 main chunks per row
__global__ void k_convert_w(const int* __restrict__ qw, const float* __restrict__ scales) {
    const float s = __ldg(scales);
    const size_t total = (size_t)N_TOT * 512;
    const size_t stride = (size_t)gridDim.x * blockDim.x;
    for (size_t id = (size_t)blockIdx.x * blockDim.x + threadIdx.x; id < total; id += stride) {
        int n = (int)(id >> 9), c = (int)(id & 511);
        const int4* p = (const int4*)(qw + ((size_t)n << 12)) + (c << 1);
        int4 a = p[0], b = p[1];
        uint4 o;
        o.x = h2u(__floats2half2_rn((float)a.x * s, (float)a.y * s));
        o.y = h2u(__floats2half2_rn((float)a.z * s, (float)a.w * s));
        o.z = h2u(__floats2half2_rn((float)b.x * s, (float)b.y * s));
        o.w = h2u(__floats2half2_rn((float)b.z * s, (float)b.w * s));
        *(uint4*)(g_wh + (size_t)n * KPAD + ((size_t)c << 3)) = o;
    }
}

// tail of g_wh rows: cols 4096..4111 = lora_B[r][n] (SCALING=1), cols 4112..4159 = 0
__global__ void k_tail_w(const float* __restrict__ lB) {
    int n = blockIdx.x;
    int t = threadIdx.x;      // 64 threads
    __half* row = g_wh + (size_t)n * KPAD;
    if (t < RANK) {
        row[K_TOT + t] = __float2half_rn(__ldg(lB + (size_t)t * N_TOT + n));
    } else {
        row[K_TOT + RANK + (t - RANK)] = __half(0.0f);
    }
}

// xA[m, r] = sum_k x[m,k] * A[k,r] -> g_xh[m, 4096+r] (fp16)
// 512 threads: 64 rows x 8 rank-pairs
__global__ void k_xa(const float* __restrict__ x, const float* __restrict__ A) {
    __shared__ float xs[64][65];
    int t = threadIdx.x;
    int m0 = blockIdx.x * 64;
    int ml = t & 63, rg = t >> 6;           // rg: 0..7, handles rank cols 2rg, 2rg+1
    float a0 = 0.f, a1 = 0.f;
    for (int kc = 0; kc < K_TOT; kc += 64) {
        #pragma unroll
        for (int j = 0; j < 2; j++) {
            int idx = t + 512 * j;          // 0..1023 float4s
            int row = idx >> 4;
            int c4  = (idx & 15) * 4;
            float4 v = *(const float4*)(x + (size_t)(m0 + row) * K_TOT + kc + c4);
            xs[row][c4] = v.x; xs[row][c4 + 1] = v.y; xs[row][c4 + 2] = v.z; xs[row][c4 + 3] = v.w;
        }
        __syncthreads();
        #pragma unroll 8
        for (int k = 0; k < 64; k++) {
            float xv = xs[ml][k];
            float2 av = __ldg((const float2*)(A + (size_t)(kc + k) * RANK + rg * 2));
            a0 += xv * av.x; a1 += xv * av.y;
        }
        __syncthreads();
    }
    __half2 h = __floats2half2_rn(a0, a1);
    *(__half2*)(g_xh + (size_t)(m0 + ml) * KPAD + K_TOT + rg * 2) = h;
}

// ---------------- main GEMM (mma.sync HMMA, 3-stage cp.async, 512 threads) ----------------
// one __syncthreads per K-chunk: next-stage loads issued BEFORE compute
#define STAGE_A 16384                      // 128 rows x 128B
#define STAGE_B 32768                      // 256 rows x 128B
#define SMEM_BYTES (NSTAGE * (STAGE_A + STAGE_B))

__global__ void __launch_bounds__(512, 1)
k_gemm(const float* __restrict__ bias, float* __restrict__ out) {
    extern __shared__ char smem[];
    const uint32_t sb = smem_u32(smem);
    const int tid  = threadIdx.x;
    const int wid  = tid >> 5;
    const int lane = tid & 31;
    const int n0 = blockIdx.x * CTA_N;
    const int m0 = blockIdx.y * CTA_M;

    const int wm = wid & 3;        // m offset wm*32
    const int wn = wid >> 2;       // n offset wn*64

    const uint32_t a_rel = (uint32_t)(wm * 32 + (lane & 15)) * 128 + ((lane >> 4) * 16);
    const uint32_t b_rel = (uint32_t)(wn * 64 + (lane & 7) + ((lane >> 4) << 3)) * 128
                         + (((lane >> 3) & 1) * 16);

    auto load_stage = [&](int s, int kc) {
        const uint32_t saA = sb + s * STAGE_A;
        const uint32_t saB = sb + NSTAGE * STAGE_A + s * STAGE_B;
        #pragma unroll
        for (int i = 0; i < 2; i++) {
            int idx = tid + 512 * i;               // 0..1023
            int row = idx >> 3, c = idx & 7;
            uint32_t off = (uint32_t)row * 128 + c * 16;
            cp16(saA + sw128(off), (const char*)(g_xh + (size_t)(m0 + row) * KPAD) + kc * 128 + c * 16);
        }
        #pragma unroll
        for (int i = 0; i < 4; i++) {
            int idx = tid + 512 * i;               // 0..2047
            int row = idx >> 3, c = idx & 7;
            uint32_t off = (uint32_t)row * 128 + c * 16;
            cp16(saB + sw128(off), (const char*)(g_wh + (size_t)(n0 + row) * KPAD) + kc * 128 + c * 16);
        }
    };

    float acc[2][8][4];
    #pragma unroll
    for (int i = 0; i < 2; i++)
        #pragma unroll
        for (int j = 0; j < 8; j++)
            #pragma unroll
            for (int r = 0; r < 4; r++) acc[i][j][r] = 0.f;

    load_stage(0, 0);
    asm volatile("cp.async.commit_group;" ::: "memory");
    load_stage(1, 1);
    asm volatile("cp.async.commit_group;" ::: "memory");

    int s = 0;
    for (int kc = 0; kc < NCHUNK; kc++) {
        asm volatile("cp.async.wait_group 1;" ::: "memory");
        __syncthreads();

        // issue next-stage loads first: stage (kc+2)%3 was last READ in iter kc-1,
        // and every thread passed the barrier above only after finishing iter kc-1.
        {
            const int lkc = kc + 2;
            int sl = s - 1; if (sl < 0) sl = NSTAGE - 1;   // (kc+2) % 3
            if (lkc < NCHUNK) load_stage(sl, lkc);
            asm volatile("cp.async.commit_group;" ::: "memory");
        }

        const uint32_t stA = sb + s * STAGE_A;
        const uint32_t stB = sb + NSTAGE * STAGE_A + s * STAGE_B;

        #pragma unroll
        for (int ks = 0; ks < 4; ks++) {
            uint32_t a[2][4];
            #pragma unroll
            for (int mt = 0; mt < 2; mt++)
                LDMX4(a[mt], stA + sw128(a_rel + (uint32_t)mt * 2048 + ks * 32));
            uint32_t b[4][4];
            #pragma unroll
            for (int p = 0; p < 4; p++)
                LDMX4(b[p], stB + sw128(b_rel + (uint32_t)p * 2048 + ks * 32));
            #pragma unroll
            for (int mt = 0; mt < 2; mt++)
                #pragma unroll
                for (int nt = 0; nt < 8; nt++)
                    MMA16816(acc[mt][nt], a[mt], &b[nt >> 1][(nt & 1) * 2]);
        }

        s = (s == NSTAGE - 1) ? 0 : s + 1;
    }

    // -------- epilogue: acc + bias -> out (fp32) --------
    const int mbase = m0 + wm * 32 + (lane >> 2);
    const int nbase = n0 + wn * 64 + (lane & 3) * 2;
    #pragma unroll
    for (int mt = 0; mt < 2; mt++) {
        const int m = mbase + mt * 16;
        #pragma unroll
        for (int nt = 0; nt < 8; nt++) {
            const int n = nbase + nt * 8;
            float2 bv = __ldg((const float2*)(bias + n));
            float2 v0 = make_float2(acc[mt][nt][0] + bv.x, acc[mt][nt][1] + bv.y);
            float2 v1 = make_float2(acc[mt][nt][2] + bv.x, acc[mt][nt][3] + bv.y);
            *(float2*)(out + (size_t)m * N_TOT + n)       = v0;
            *(float2*)(out + (size_t)(m + 8) * N_TOT + n) = v1;
        }
    }
}

// ---------------- launch ----------------
extern "C" void kernel_launch(void* const* d_in, const int* in_sizes, int n_in,
                              void* d_out, int out_size) {
    (void)in_sizes; (void)n_in; (void)out_size;
    const float* x      = (const float*)d_in[0];
    const int*   qw     = (const int*)d_in[1];
    const float* scales = (const float*)d_in[2];
    const float* bias   = (const float*)d_in[3];
    const float* lA     = (const float*)d_in[4];
    const float* lB     = (const float*)d_in[5];
    float* out = (float*)d_out;

    cudaFuncSetAttribute(k_gemm, cudaFuncAttributeMaxDynamicSharedMemorySize, SMEM_BYTES);

    k_convert_x<<<4096, 256>>>(x);                 // grid-stride, 2 chunks/thread
    k_pad_x<<<(M_TOT * 8) / 256, 256>>>();
    k_convert_w<<<2048, 256>>>(qw, scales);
    k_tail_w<<<N_TOT, 64>>>(lB);
    k_xa<<<M_TOT / 64, 512>>>(x, lA);

    dim3 grid(N_TOT / CTA_N, M_TOT / CTA_M);
    k_gemm<<<grid, 512, SMEM_BYTES>>>(bias, out);
}

// round 7
// speedup vs baseline: 1.2977x; 1.2977x over previous
#include <cuda_runtime.h>
#include <cuda_fp16.h>
#include <cstdint>
#include <cstddef>

// ---------------- problem constants ----------------
#define M_TOT   8192          // B*S
#define N_TOT   4096          // D_OUT
#define K_TOT   4096          // D_IN
#define RANK    16
#define KPAD    4160          // 4096 + 16 lora + 48 pad = 65 * 64
#define NCHUNK  65            // KPAD / 64
#define CTA_M   128
#define CTA_N   128
#define NSTAGE  4

// scratch (device globals: allocation-free scratch)
__device__ __half g_xh[(size_t)M_TOT * KPAD];   // x (fp16) + lora/pad cols
__device__ __half g_wh[(size_t)N_TOT * KPAD];   // w = q*scale (fp16) + loraB/pad cols

// ---------------- helpers ----------------
__device__ __forceinline__ uint32_t smem_u32(const void* p) {
    uint32_t a;
    asm("{ .reg .u64 t; cvta.to.shared.u64 t, %1; cvt.u32.u64 %0, t; }" : "=r"(a) : "l"(p));
    return a;
}
__device__ __forceinline__ void cp16(uint32_t smem_dst, const void* gmem_src) {
    asm volatile("cp.async.cg.shared.global [%0], [%1], 16;" :: "r"(smem_dst), "l"(gmem_src) : "memory");
}
__device__ __forceinline__ uint32_t sw128(uint32_t off) { return off ^ ((off >> 3) & 0x70); }

#define LDMX4(r, addr) \
    asm volatile("ldmatrix.sync.aligned.m8n8.x4.shared.b16 {%0,%1,%2,%3}, [%4];" \
        : "=r"((r)[0]), "=r"((r)[1]), "=r"((r)[2]), "=r"((r)[3]) : "r"(addr))

#define MMA16816(c, a, b) \
    asm volatile("mma.sync.aligned.m16n8k16.row.col.f32.f16.f16.f32 " \
        "{%0,%1,%2,%3}, {%4,%5,%6,%7}, {%8,%9}, {%0,%1,%2,%3};" \
        : "+f"((c)[0]), "+f"((c)[1]), "+f"((c)[2]), "+f"((c)[3]) \
        : "r"((a)[0]), "r"((a)[1]), "r"((a)[2]), "r"((a)[3]), "r"((b)[0]), "r"((b)[1]))

__device__ __forceinline__ uint32_t h2u(__half2 h) { return *(uint32_t*)&h; }

// ---------------- pre-pass kernels ----------------

__global__ void k_convert_x(const float* __restrict__ x) {
    const size_t total = (size_t)M_TOT * 512;
    const size_t stride = (size_t)gridDim.x * blockDim.x;
    for (size_t id = (size_t)blockIdx.x * blockDim.x + threadIdx.x; id < total; id += stride) {
        int m = (int)(id >> 9), c = (int)(id & 511);
        const float4* p = (const float4*)(x + ((size_t)m << 12)) + (c << 1);
        float4 a = p[0], b = p[1];
        uint4 o;
        o.x = h2u(__floats2half2_rn(a.x, a.y));
        o.y = h2u(__floats2half2_rn(a.z, a.w));
        o.z = h2u(__floats2half2_rn(b.x, b.y));
        o.w = h2u(__floats2half2_rn(b.z, b.w));
        *(uint4*)(g_xh + (size_t)m * KPAD + ((size_t)c << 3)) = o;
    }
}

__global__ void k_pad_x() {
    int id = blockIdx.x * blockDim.x + threadIdx.x;   // 8192*8
    int m = id >> 3, c = id & 7;
    if (c >= 6) return;
    uint4 z = {0, 0, 0, 0};
    *(uint4*)(g_xh + (size_t)m * KPAD + 4112 + (c << 3)) = z;
}

__global__ void k_convert_w(const int* __restrict__ qw, const float* __restrict__ scales) {
    const float s = __ldg(scales);
    const size_t total = (size_t)N_TOT * 512;
    const size_t stride = (size_t)gridDim.x * blockDim.x;
    for (size_t id = (size_t)blockIdx.x * blockDim.x + threadIdx.x; id < total; id += stride) {
        int n = (int)(id >> 9), c = (int)(id & 511);
        const int4* p = (const int4*)(qw + ((size_t)n << 12)) + (c << 1);
        int4 a = p[0], b = p[1];
        uint4 o;
        o.x = h2u(__floats2half2_rn((float)a.x * s, (float)a.y * s));
        o.y = h2u(__floats2half2_rn((float)a.z * s, (float)a.w * s));
        o.z = h2u(__floats2half2_rn((float)b.x * s, (float)b.y * s));
        o.w = h2u(__floats2half2_rn((float)b.z * s, (float)b.w * s));
        *(uint4*)(g_wh + (size_t)n * KPAD + ((size_t)c << 3)) = o;
    }
}

__global__ void k_tail_w(const float* __restrict__ lB) {
    int n = blockIdx.x;
    int t = threadIdx.x;      // 64 threads
    __half* row = g_wh + (size_t)n * KPAD;
    if (t < RANK) {
        row[K_TOT + t] = __float2half_rn(__ldg(lB + (size_t)t * N_TOT + n));
    } else {
        row[K_TOT + RANK + (t - RANK)] = __half(0.0f);
    }
}

// xA[m, r] = sum_k x[m,k] * A[k,r] -> g_xh[m, 4096+r] (fp16)
__global__ void k_xa(const float* __restrict__ x, const float* __restrict__ A) {
    __shared__ float xs[64][65];
    int t = threadIdx.x;
    int m0 = blockIdx.x * 64;
    int ml = t & 63, rg = t >> 6;           // rg: 0..7 -> rank cols 2rg, 2rg+1
    float a0 = 0.f, a1 = 0.f;
    for (int kc = 0; kc < K_TOT; kc += 64) {
        #pragma unroll
        for (int j = 0; j < 2; j++) {
            int idx = t + 512 * j;          // 0..1023 float4s
            int row = idx >> 4;
            int c4  = (idx & 15) * 4;
            float4 v = *(const float4*)(x + (size_t)(m0 + row) * K_TOT + kc + c4);
            xs[row][c4] = v.x; xs[row][c4 + 1] = v.y; xs[row][c4 + 2] = v.z; xs[row][c4 + 3] = v.w;
        }
        __syncthreads();
        #pragma unroll 8
        for (int k = 0; k < 64; k++) {
            float xv = xs[ml][k];
            float2 av = __ldg((const float2*)(A + (size_t)(kc + k) * RANK + rg * 2));
            a0 += xv * av.x; a1 += xv * av.y;
        }
        __syncthreads();
    }
    __half2 h = __floats2half2_rn(a0, a1);
    *(__half2*)(g_xh + (size_t)(m0 + ml) * KPAD + K_TOT + rg * 2) = h;
}

// ---------------- main GEMM (mma.sync HMMA, 256 threads, 4-stage, reg double-buffer) ----------------
#define STAGE_BYTES 16384
#define SMEM_BYTES  (2 * NSTAGE * STAGE_BYTES)

__global__ void __launch_bounds__(256, 1)
k_gemm(const float* __restrict__ bias, float* __restrict__ out) {
    extern __shared__ char smem[];
    const uint32_t sb = smem_u32(smem);
    const int tid  = threadIdx.x;
    const int wid  = tid >> 5;
    const int lane = tid & 31;
    const int n0 = blockIdx.x * CTA_N;
    const int m0 = blockIdx.y * CTA_M;

    const int wm = wid & 1;        // m offset wm*64
    const int wn = wid >> 1;       // n offset wn*32

    const uint32_t a_rel = (uint32_t)(wm * 64 + (lane & 15)) * 128 + ((lane >> 4) * 16);
    const uint32_t b_rel = (uint32_t)(wn * 32 + (lane & 7) + ((lane >> 4) << 3)) * 128
                         + (((lane >> 3) & 1) * 16);

    auto load_stage = [&](int s, int kc) {
        const uint32_t saA = sb + s * STAGE_BYTES;
        const uint32_t saB = sb + NSTAGE * STAGE_BYTES + s * STAGE_BYTES;
        #pragma unroll
        for (int i = 0; i < 4; i++) {
            int idx = tid + 256 * i;            // 0..1023
            int row = idx >> 3, c = idx & 7;
            uint32_t off = (uint32_t)row * 128 + c * 16;
            cp16(saA + sw128(off), (const char*)(g_xh + (size_t)(m0 + row) * KPAD) + kc * 128 + c * 16);
            cp16(saB + sw128(off), (const char*)(g_wh + (size_t)(n0 + row) * KPAD) + kc * 128 + c * 16);
        }
    };

    float acc[4][4][4];
    #pragma unroll
    for (int i = 0; i < 4; i++)
        #pragma unroll
        for (int j = 0; j < 4; j++)
            #pragma unroll
            for (int r = 0; r < 4; r++) acc[i][j][r] = 0.f;

    // prologue: 3 stages in flight
    #pragma unroll
    for (int s = 0; s < 3; s++) {
        load_stage(s, s);
        asm volatile("cp.async.commit_group;" ::: "memory");
    }

    for (int kc = 0; kc < NCHUNK; kc++) {
        asm volatile("cp.async.wait_group 2;" ::: "memory");
        __syncthreads();

        // issue next-stage loads first; stage (kc+3)%4 == (kc-1)%4 was last read
        // in iter kc-1 and all warps have passed the barrier above.
        {
            const int lkc = kc + 3;
            if (lkc < NCHUNK) load_stage(lkc & (NSTAGE - 1), lkc);
            asm volatile("cp.async.commit_group;" ::: "memory");
        }

        const int s = kc & (NSTAGE - 1);
        const uint32_t stA = sb + s * STAGE_BYTES;
        const uint32_t stB = sb + NSTAGE * STAGE_BYTES + s * STAGE_BYTES;

        // register double-buffered ks pipeline
        uint32_t a[2][4][4], b[2][2][4];
        #pragma unroll
        for (int mt = 0; mt < 4; mt++)
            LDMX4(a[0][mt], stA + sw128(a_rel + (uint32_t)mt * 2048));
        #pragma unroll
        for (int p = 0; p < 2; p++)
            LDMX4(b[0][p], stB + sw128(b_rel + (uint32_t)p * 2048));

        #pragma unroll
        for (int ks = 0; ks < 4; ks++) {
            const int cb = ks & 1, nb = cb ^ 1;
            if (ks < 3) {
                #pragma unroll
                for (int mt = 0; mt < 4; mt++)
                    LDMX4(a[nb][mt], stA + sw128(a_rel + (uint32_t)mt * 2048 + (ks + 1) * 32));
                #pragma unroll
                for (int p = 0; p < 2; p++)
                    LDMX4(b[nb][p], stB + sw128(b_rel + (uint32_t)p * 2048 + (ks + 1) * 32));
            }
            #pragma unroll
            for (int mt = 0; mt < 4; mt++)
                #pragma unroll
                for (int nt = 0; nt < 4; nt++)
                    MMA16816(acc[mt][nt], a[cb][mt], &b[cb][nt >> 1][(nt & 1) * 2]);
        }
    }

    // -------- epilogue: acc + bias -> out (fp32) --------
    #pragma unroll
    for (int mt = 0; mt < 4; mt++) {
        const int m = m0 + wm * 64 + mt * 16 + (lane >> 2);
        #pragma unroll
        for (int nt = 0; nt < 4; nt++) {
            const int n = n0 + wn * 32 + nt * 8 + (lane & 3) * 2;
            float2 bv = __ldg((const float2*)(bias + n));
            float2 v0 = make_float2(acc[mt][nt][0] + bv.x, acc[mt][nt][1] + bv.y);
            float2 v1 = make_float2(acc[mt][nt][2] + bv.x, acc[mt][nt][3] + bv.y);
            *(float2*)(out + (size_t)m * N_TOT + n)       = v0;
            *(float2*)(out + (size_t)(m + 8) * N_TOT + n) = v1;
        }
    }
}

// ---------------- launch ----------------
extern "C" void kernel_launch(void* const* d_in, const int* in_sizes, int n_in,
                              void* d_out, int out_size) {
    (void)in_sizes; (void)n_in; (void)out_size;
    const float* x      = (const float*)d_in[0];
    const int*   qw     = (const int*)d_in[1];
    const float* scales = (const float*)d_in[2];
    const float* bias   = (const float*)d_in[3];
    const float* lA     = (const float*)d_in[4];
    const float* lB     = (const float*)d_in[5];
    float* out = (float*)d_out;

    cudaFuncSetAttribute(k_gemm, cudaFuncAttributeMaxDynamicSharedMemorySize, SMEM_BYTES);

    k_convert_x<<<4096, 256>>>(x);
    k_pad_x<<<(M_TOT * 8) / 256, 256>>>();
    k_convert_w<<<2048, 256>>>(qw, scales);
    k_tail_w<<<N_TOT, 64>>>(lB);
    k_xa<<<M_TOT / 64, 512>>>(x, lA);

    dim3 grid(N_TOT / CTA_N, M_TOT / CTA_M);
    k_gemm<<<grid, 256, SMEM_BYTES>>>(bias, out);
}

// round 8
// speedup vs baseline: 1.4096x; 1.0862x over previous
#include <cuda_runtime.h>
#include <cuda_fp16.h>
#include <cstdint>
#include <cstddef>

// ---------------- problem constants ----------------
#define M_TOT   8192          // B*S
#define N_TOT   4096          // D_OUT
#define K_TOT   4096          // D_IN
#define RANK    16
#define KPAD    4160          // 4096 + 16 lora + 48 pad = 65 * 64
#define NCHUNK  65            // KPAD / 64
#define CTA_M   128
#define CTA_N   128
#define NSTAGE  5

// scratch (device globals: allocation-free scratch)
__device__ __half g_xh[(size_t)M_TOT * KPAD];   // x (fp16) + lora/pad cols
__device__ __half g_wh[(size_t)N_TOT * KPAD];   // w = q*scale (fp16) + loraB/pad cols

// ---------------- helpers ----------------
__device__ __forceinline__ uint32_t smem_u32(const void* p) {
    uint32_t a;
    asm("{ .reg .u64 t; cvta.to.shared.u64 t, %1; cvt.u32.u64 %0, t; }" : "=r"(a) : "l"(p));
    return a;
}
__device__ __forceinline__ void cp16(uint32_t smem_dst, const void* gmem_src) {
    asm volatile("cp.async.cg.shared.global [%0], [%1], 16;" :: "r"(smem_dst), "l"(gmem_src) : "memory");
}
__device__ __forceinline__ uint32_t sw128(uint32_t off) { return off ^ ((off >> 3) & 0x70); }

#define LDMX4(r, addr) \
    asm volatile("ldmatrix.sync.aligned.m8n8.x4.shared.b16 {%0,%1,%2,%3}, [%4];" \
        : "=r"((r)[0]), "=r"((r)[1]), "=r"((r)[2]), "=r"((r)[3]) : "r"(addr))

#define MMA16816(c, a, b) \
    asm volatile("mma.sync.aligned.m16n8k16.row.col.f32.f16.f16.f32 " \
        "{%0,%1,%2,%3}, {%4,%5,%6,%7}, {%8,%9}, {%0,%1,%2,%3};" \
        : "+f"((c)[0]), "+f"((c)[1]), "+f"((c)[2]), "+f"((c)[3]) \
        : "r"((a)[0]), "r"((a)[1]), "r"((a)[2]), "r"((a)[3]), "r"((b)[0]), "r"((b)[1]))

__device__ __forceinline__ uint32_t h2u(__half2 h) { return *(uint32_t*)&h; }

// ---------------- pre-pass kernels ----------------

__global__ void k_convert_x(const float* __restrict__ x) {
    const size_t total = (size_t)M_TOT * 512;
    const size_t stride = (size_t)gridDim.x * blockDim.x;
    for (size_t id = (size_t)blockIdx.x * blockDim.x + threadIdx.x; id < total; id += stride) {
        int m = (int)(id >> 9), c = (int)(id & 511);
        const float4* p = (const float4*)(x + ((size_t)m << 12)) + (c << 1);
        float4 a = p[0], b = p[1];
        uint4 o;
        o.x = h2u(__floats2half2_rn(a.x, a.y));
        o.y = h2u(__floats2half2_rn(a.z, a.w));
        o.z = h2u(__floats2half2_rn(b.x, b.y));
        o.w = h2u(__floats2half2_rn(b.z, b.w));
        *(uint4*)(g_xh + (size_t)m * KPAD + ((size_t)c << 3)) = o;
    }
}

__global__ void k_pad_x() {
    int id = blockIdx.x * blockDim.x + threadIdx.x;   // 8192*8
    int m = id >> 3, c = id & 7;
    if (c >= 6) return;
    uint4 z = {0, 0, 0, 0};
    *(uint4*)(g_xh + (size_t)m * KPAD + 4112 + (c << 3)) = z;
}

__global__ void k_convert_w(const int* __restrict__ qw, const float* __restrict__ scales) {
    const float s = __ldg(scales);
    const size_t total = (size_t)N_TOT * 512;
    const size_t stride = (size_t)gridDim.x * blockDim.x;
    for (size_t id = (size_t)blockIdx.x * blockDim.x + threadIdx.x; id < total; id += stride) {
        int n = (int)(id >> 9), c = (int)(id & 511);
        const int4* p = (const int4*)(qw + ((size_t)n << 12)) + (c << 1);
        int4 a = p[0], b = p[1];
        uint4 o;
        o.x = h2u(__floats2half2_rn((float)a.x * s, (float)a.y * s));
        o.y = h2u(__floats2half2_rn((float)a.z * s, (float)a.w * s));
        o.z = h2u(__floats2half2_rn((float)b.x * s, (float)b.y * s));
        o.w = h2u(__floats2half2_rn((float)b.z * s, (float)b.w * s));
        *(uint4*)(g_wh + (size_t)n * KPAD + ((size_t)c << 3)) = o;
    }
}

__global__ void k_tail_w(const float* __restrict__ lB) {
    int n = blockIdx.x;
    int t = threadIdx.x;      // 64 threads
    __half* row = g_wh + (size_t)n * KPAD;
    if (t < RANK) {
        row[K_TOT + t] = __float2half_rn(__ldg(lB + (size_t)t * N_TOT + n));
    } else {
        row[K_TOT + RANK + (t - RANK)] = __half(0.0f);
    }
}

// xA[m, r] = sum_k x[m,k] * A[k,r] -> g_xh[m, 4096+r] (fp16)
// 256 blocks x 512 threads: 32 rows/block, one rank-col per thread group
__global__ void k_xa(const float* __restrict__ x, const float* __restrict__ A) {
    __shared__ float xs[32][65];
    int t = threadIdx.x;
    int m0 = blockIdx.x * 32;
    int ml = t & 31, rg = t >> 5;           // rg: 0..15 -> rank col rg
    float a0 = 0.f;
    for (int kc = 0; kc < K_TOT; kc += 64) {
        {
            int row = t >> 4;               // 0..31
            int c4  = (t & 15) * 4;
            float4 v = *(const float4*)(x + (size_t)(m0 + row) * K_TOT + kc + c4);
            xs[row][c4] = v.x; xs[row][c4 + 1] = v.y; xs[row][c4 + 2] = v.z; xs[row][c4 + 3] = v.w;
        }
        __syncthreads();
        #pragma unroll 8
        for (int k = 0; k < 64; k++)
            a0 += xs[ml][k] * __ldg(A + (size_t)(kc + k) * RANK + rg);
        __syncthreads();
    }
    g_xh[(size_t)(m0 + ml) * KPAD + K_TOT + rg] = __float2half_rn(a0);
}

// ---------------- main GEMM: 512 threads, warp tile 32x32, 5-stage ----------------
#define STAGE_BYTES 16384
#define SMEM_BYTES  (2 * NSTAGE * STAGE_BYTES)

__global__ void __launch_bounds__(512, 1)
k_gemm(const float* __restrict__ bias, float* __restrict__ out) {
    extern __shared__ char smem[];
    const uint32_t sb = smem_u32(smem);
    const int tid  = threadIdx.x;
    const int wid  = tid >> 5;
    const int lane = tid & 31;
    const int n0 = blockIdx.x * CTA_N;
    const int m0 = blockIdx.y * CTA_M;

    const int wm = wid & 3;        // m offset wm*32
    const int wn = wid >> 2;       // n offset wn*32

    const uint32_t a_rel = (uint32_t)(wm * 32 + (lane & 15)) * 128 + ((lane >> 4) * 16);
    const uint32_t b_rel = (uint32_t)(wn * 32 + (lane & 7) + ((lane >> 4) << 3)) * 128
                         + (((lane >> 3) & 1) * 16);

    auto load_stage = [&](int s, int kc) {
        const uint32_t saA = sb + s * STAGE_BYTES;
        const uint32_t saB = sb + NSTAGE * STAGE_BYTES + s * STAGE_BYTES;
        #pragma unroll
        for (int i = 0; i < 2; i++) {
            int idx = tid + 512 * i;            // 0..1023
            int row = idx >> 3, c = idx & 7;
            uint32_t off = (uint32_t)row * 128 + c * 16;
            cp16(saA + sw128(off), (const char*)(g_xh + (size_t)(m0 + row) * KPAD) + kc * 128 + c * 16);
            cp16(saB + sw128(off), (const char*)(g_wh + (size_t)(n0 + row) * KPAD) + kc * 128 + c * 16);
        }
    };

    float acc[2][4][4];
    #pragma unroll
    for (int i = 0; i < 2; i++)
        #pragma unroll
        for (int j = 0; j < 4; j++)
            #pragma unroll
            for (int r = 0; r < 4; r++) acc[i][j][r] = 0.f;

    // prologue: NSTAGE-1 stages in flight
    #pragma unroll
    for (int s = 0; s < NSTAGE - 1; s++) {
        load_stage(s, s);
        asm volatile("cp.async.commit_group;" ::: "memory");
    }

    int s = 0;
    for (int kc = 0; kc < NCHUNK; kc++) {
        asm volatile("cp.async.wait_group %0;" :: "n"(NSTAGE - 2) : "memory");
        __syncthreads();

        // prefetch next stage first; stage (kc+NSTAGE-1)%NSTAGE == (kc-1)%NSTAGE
        // was last read in iter kc-1, protected by the barrier above.
        {
            const int lkc = kc + NSTAGE - 1;
            int sl = s - 1; if (sl < 0) sl = NSTAGE - 1;
            if (lkc < NCHUNK) load_stage(sl, lkc);
            asm volatile("cp.async.commit_group;" ::: "memory");
        }

        const uint32_t stA = sb + s * STAGE_BYTES;
        const uint32_t stB = sb + NSTAGE * STAGE_BYTES + s * STAGE_BYTES;

        // register double-buffered ks pipeline
        uint32_t a[2][2][4], b[2][2][4];
        #pragma unroll
        for (int mt = 0; mt < 2; mt++)
            LDMX4(a[0][mt], stA + sw128(a_rel + (uint32_t)mt * 2048));
        #pragma unroll
        for (int p = 0; p < 2; p++)
            LDMX4(b[0][p], stB + sw128(b_rel + (uint32_t)p * 2048));

        #pragma unroll
        for (int ks = 0; ks < 4; ks++) {
            const int cb = ks & 1, nb = cb ^ 1;
            if (ks < 3) {
                #pragma unroll
                for (int mt = 0; mt < 2; mt++)
                    LDMX4(a[nb][mt], stA + sw128(a_rel + (uint32_t)mt * 2048 + (ks + 1) * 32));
                #pragma unroll
                for (int p = 0; p < 2; p++)
                    LDMX4(b[nb][p], stB + sw128(b_rel + (uint32_t)p * 2048 + (ks + 1) * 32));
            }
            #pragma unroll
            for (int mt = 0; mt < 2; mt++)
                #pragma unroll
                for (int nt = 0; nt < 4; nt++)
                    MMA16816(acc[mt][nt], a[cb][mt], &b[cb][nt >> 1][(nt & 1) * 2]);
        }

        s = (s == NSTAGE - 1) ? 0 : s + 1;
    }

    // -------- epilogue: acc + bias -> out (fp32) --------
    #pragma unroll
    for (int mt = 0; mt < 2; mt++) {
        const int m = m0 + wm * 32 + mt * 16 + (lane >> 2);
        #pragma unroll
        for (int nt = 0; nt < 4; nt++) {
            const int n = n0 + wn * 32 + nt * 8 + (lane & 3) * 2;
            float2 bv = __ldg((const float2*)(bias + n));
            float2 v0 = make_float2(acc[mt][nt][0] + bv.x, acc[mt][nt][1] + bv.y);
            float2 v1 = make_float2(acc[mt][nt][2] + bv.x, acc[mt][nt][3] + bv.y);
            *(float2*)(out + (size_t)m * N_TOT + n)       = v0;
            *(float2*)(out + (size_t)(m + 8) * N_TOT + n) = v1;
        }
    }
}

// ---------------- launch ----------------
extern "C" void kernel_launch(void* const* d_in, const int* in_sizes, int n_in,
                              void* d_out, int out_size) {
    (void)in_sizes; (void)n_in; (void)out_size;
    const float* x      = (const float*)d_in[0];
    const int*   qw     = (const int*)d_in[1];
    const float* scales = (const float*)d_in[2];
    const float* bias   = (const float*)d_in[3];
    const float* lA     = (const float*)d_in[4];
    const float* lB     = (const float*)d_in[5];
    float* out = (float*)d_out;

    cudaFuncSetAttribute(k_gemm, cudaFuncAttributeMaxDynamicSharedMemorySize, SMEM_BYTES);

    k_convert_x<<<4096, 256>>>(x);
    k_pad_x<<<(M_TOT * 8) / 256, 256>>>();
    k_convert_w<<<2048, 256>>>(qw, scales);
    k_tail_w<<<N_TOT, 64>>>(lB);
    k_xa<<<M_TOT / 32, 512>>>(x, lA);

    dim3 grid(N_TOT / CTA_N, M_TOT / CTA_M);
    k_gemm<<<grid, 512, SMEM_BYTES>>>(bias, out);
}

// round 9
// speedup vs baseline: 1.6454x; 1.1673x over previous
#include <cuda_runtime.h>
#include <cuda_fp16.h>
#include <cstdint>
#include <cstddef>

// ---------------- problem constants ----------------
#define M_TOT   8192          // B*S
#define N_TOT   4096          // D_OUT
#define K_TOT   4096          // D_IN
#define RANK    16
#define KPAD    4160          // 4096 + 16 lora + 48 pad = 65 * 64
#define NCHUNK  65            // KPAD / 64
#define CTA_M   256
#define CTA_N   128
#define NSTAGE  4

// scratch (device globals: allocation-free scratch)
__device__ __half g_xh[(size_t)M_TOT * KPAD];   // x (fp16) + lora/pad cols
__device__ __half g_wh[(size_t)N_TOT * KPAD];   // w = q*scale (fp16) + loraB/pad cols

// ---------------- helpers ----------------
__device__ __forceinline__ uint32_t smem_u32(const void* p) {
    uint32_t a;
    asm("{ .reg .u64 t; cvta.to.shared.u64 t, %1; cvt.u32.u64 %0, t; }" : "=r"(a) : "l"(p));
    return a;
}
__device__ __forceinline__ void cp16(uint32_t smem_dst, const void* gmem_src) {
    asm volatile("cp.async.cg.shared.global [%0], [%1], 16;" :: "r"(smem_dst), "l"(gmem_src) : "memory");
}
__device__ __forceinline__ uint32_t sw128(uint32_t off) { return off ^ ((off >> 3) & 0x70); }

#define LDMX4(r, addr) \
    asm volatile("ldmatrix.sync.aligned.m8n8.x4.shared.b16 {%0,%1,%2,%3}, [%4];" \
        : "=r"((r)[0]), "=r"((r)[1]), "=r"((r)[2]), "=r"((r)[3]) : "r"(addr))

#define MMA16816(c, a, b) \
    asm volatile("mma.sync.aligned.m16n8k16.row.col.f32.f16.f16.f32 " \
        "{%0,%1,%2,%3}, {%4,%5,%6,%7}, {%8,%9}, {%0,%1,%2,%3};" \
        : "+f"((c)[0]), "+f"((c)[1]), "+f"((c)[2]), "+f"((c)[3]) \
        : "r"((a)[0]), "r"((a)[1]), "r"((a)[2]), "r"((a)[3]), "r"((b)[0]), "r"((b)[1]))

__device__ __forceinline__ uint32_t h2u(__half2 h) { return *(uint32_t*)&h; }

// ---------------- pre-pass kernels ----------------

__global__ void k_convert_x(const float* __restrict__ x) {
    const size_t total = (size_t)M_TOT * 512;
    const size_t stride = (size_t)gridDim.x * blockDim.x;
    for (size_t id = (size_t)blockIdx.x * blockDim.x + threadIdx.x; id < total; id += stride) {
        int m = (int)(id >> 9), c = (int)(id & 511);
        const float4* p = (const float4*)(x + ((size_t)m << 12)) + (c << 1);
        float4 a = p[0], b = p[1];
        uint4 o;
        o.x = h2u(__floats2half2_rn(a.x, a.y));
        o.y = h2u(__floats2half2_rn(a.z, a.w));
        o.z = h2u(__floats2half2_rn(b.x, b.y));
        o.w = h2u(__floats2half2_rn(b.z, b.w));
        *(uint4*)(g_xh + (size_t)m * KPAD + ((size_t)c << 3)) = o;
    }
}

__global__ void k_pad_x() {
    int id = blockIdx.x * blockDim.x + threadIdx.x;   // 8192*8
    int m = id >> 3, c = id & 7;
    if (c >= 6) return;
    uint4 z = {0, 0, 0, 0};
    *(uint4*)(g_xh + (size_t)m * KPAD + 4112 + (c << 3)) = z;
}

__global__ void k_convert_w(const int* __restrict__ qw, const float* __restrict__ scales) {
    const float s = __ldg(scales);
    const size_t total = (size_t)N_TOT * 512;
    const size_t stride = (size_t)gridDim.x * blockDim.x;
    for (size_t id = (size_t)blockIdx.x * blockDim.x + threadIdx.x; id < total; id += stride) {
        int n = (int)(id >> 9), c = (int)(id & 511);
        const int4* p = (const int4*)(qw + ((size_t)n << 12)) + (c << 1);
        int4 a = p[0], b = p[1];
        uint4 o;
        o.x = h2u(__floats2half2_rn((float)a.x * s, (float)a.y * s));
        o.y = h2u(__floats2half2_rn((float)a.z * s, (float)a.w * s));
        o.z = h2u(__floats2half2_rn((float)b.x * s, (float)b.y * s));
        o.w = h2u(__floats2half2_rn((float)b.z * s, (float)b.w * s));
        *(uint4*)(g_wh + (size_t)n * KPAD + ((size_t)c << 3)) = o;
    }
}

__global__ void k_tail_w(const float* __restrict__ lB) {
    int n = blockIdx.x;
    int t = threadIdx.x;      // 64 threads
    __half* row = g_wh + (size_t)n * KPAD;
    if (t < RANK) {
        row[K_TOT + t] = __float2half_rn(__ldg(lB + (size_t)t * N_TOT + n));
    } else {
        row[K_TOT + RANK + (t - RANK)] = __half(0.0f);
    }
}

// xA[m, r] = sum_k x[m,k] * A[k,r] -> g_xh[m, 4096+r] (fp16)
__global__ void k_xa(const float* __restrict__ x, const float* __restrict__ A) {
    __shared__ float xs[32][65];
    int t = threadIdx.x;
    int m0 = blockIdx.x * 32;
    int ml = t & 31, rg = t >> 5;           // rg: 0..15 -> rank col rg
    float a0 = 0.f;
    for (int kc = 0; kc < K_TOT; kc += 64) {
        {
            int row = t >> 4;               // 0..31
            int c4  = (t & 15) * 4;
            float4 v = *(const float4*)(x + (size_t)(m0 + row) * K_TOT + kc + c4);
            xs[row][c4] = v.x; xs[row][c4 + 1] = v.y; xs[row][c4 + 2] = v.z; xs[row][c4 + 3] = v.w;
        }
        __syncthreads();
        #pragma unroll 8
        for (int k = 0; k < 64; k++)
            a0 += xs[ml][k] * __ldg(A + (size_t)(kc + k) * RANK + rg);
        __syncthreads();
    }
    g_xh[(size_t)(m0 + ml) * KPAD + K_TOT + rg] = __float2half_rn(a0);
}

// ---------------- main GEMM: 512 threads, CTA 256x128, warp tile 64x32, 4-stage ----------------
#define STAGE_A 32768                      // 256 rows x 128B
#define STAGE_B 16384                      // 128 rows x 128B
#define SMEM_BYTES (NSTAGE * (STAGE_A + STAGE_B))

__global__ void __launch_bounds__(512, 1)
k_gemm(const float* __restrict__ bias, float* __restrict__ out) {
    extern __shared__ char smem[];
    const uint32_t sb = smem_u32(smem);
    const int tid  = threadIdx.x;
    const int wid  = tid >> 5;
    const int lane = tid & 31;
    const int n0 = blockIdx.x * CTA_N;
    const int m0 = blockIdx.y * CTA_M;

    const int wm = wid & 3;        // m offset wm*64
    const int wn = wid >> 2;       // n offset wn*32

    const uint32_t a_rel = (uint32_t)(wm * 64 + (lane & 15)) * 128 + ((lane >> 4) * 16);
    const uint32_t b_rel = (uint32_t)(wn * 32 + (lane & 7) + ((lane >> 4) << 3)) * 128
                         + (((lane >> 3) & 1) * 16);

    auto load_stage = [&](int s, int kc) {
        const uint32_t saA = sb + s * STAGE_A;
        const uint32_t saB = sb + NSTAGE * STAGE_A + s * STAGE_B;
        #pragma unroll
        for (int i = 0; i < 4; i++) {              // A: 2048 cp16
            int idx = tid + 512 * i;
            int row = idx >> 3, c = idx & 7;
            uint32_t off = (uint32_t)row * 128 + c * 16;
            cp16(saA + sw128(off), (const char*)(g_xh + (size_t)(m0 + row) * KPAD) + kc * 128 + c * 16);
        }
        #pragma unroll
        for (int i = 0; i < 2; i++) {              // B: 1024 cp16
            int idx = tid + 512 * i;
            int row = idx >> 3, c = idx & 7;
            uint32_t off = (uint32_t)row * 128 + c * 16;
            cp16(saB + sw128(off), (const char*)(g_wh + (size_t)(n0 + row) * KPAD) + kc * 128 + c * 16);
        }
    };

    float acc[4][4][4];
    #pragma unroll
    for (int i = 0; i < 4; i++)
        #pragma unroll
        for (int j = 0; j < 4; j++)
            #pragma unroll
            for (int r = 0; r < 4; r++) acc[i][j][r] = 0.f;

    // prologue: NSTAGE-1 stages in flight
    #pragma unroll
    for (int s = 0; s < NSTAGE - 1; s++) {
        load_stage(s, s);
        asm volatile("cp.async.commit_group;" ::: "memory");
    }

    for (int kc = 0; kc < NCHUNK; kc++) {
        asm volatile("cp.async.wait_group %0;" :: "n"(NSTAGE - 2) : "memory");
        __syncthreads();

        // prefetch next stage first; the overwritten stage was last read in iter
        // kc-1, and all warps have passed the barrier above.
        {
            const int lkc = kc + NSTAGE - 1;
            if (lkc < NCHUNK) load_stage(lkc & (NSTAGE - 1), lkc);
            asm volatile("cp.async.commit_group;" ::: "memory");
        }

        const int s = kc & (NSTAGE - 1);
        const uint32_t stA = sb + s * STAGE_A;
        const uint32_t stB = sb + NSTAGE * STAGE_A + s * STAGE_B;

        #pragma unroll
        for (int ks = 0; ks < 4; ks++) {
            uint32_t a[4][4], b[2][4];
            #pragma unroll
            for (int mt = 0; mt < 4; mt++)
                LDMX4(a[mt], stA + sw128(a_rel + (uint32_t)mt * 2048 + ks * 32));
            #pragma unroll
            for (int p = 0; p < 2; p++)
                LDMX4(b[p], stB + sw128(b_rel + (uint32_t)p * 2048 + ks * 32));
            #pragma unroll
            for (int mt = 0; mt < 4; mt++)
                #pragma unroll
                for (int nt = 0; nt < 4; nt++)
                    MMA16816(acc[mt][nt], a[mt], &b[nt >> 1][(nt & 1) * 2]);
        }
    }

    // -------- epilogue: acc + bias -> out (fp32) --------
    #pragma unroll
    for (int mt = 0; mt < 4; mt++) {
        const int m = m0 + wm * 64 + mt * 16 + (lane >> 2);
        #pragma unroll
        for (int nt = 0; nt < 4; nt++) {
            const int n = n0 + wn * 32 + nt * 8 + (lane & 3) * 2;
            float2 bv = __ldg((const float2*)(bias + n));
            float2 v0 = make_float2(acc[mt][nt][0] + bv.x, acc[mt][nt][1] + bv.y);
            float2 v1 = make_float2(acc[mt][nt][2] + bv.x, acc[mt][nt][3] + bv.y);
            *(float2*)(out + (size_t)m * N_TOT + n)       = v0;
            *(float2*)(out + (size_t)(m + 8) * N_TOT + n) = v1;
        }
    }
}

// ---------------- launch ----------------
extern "C" void kernel_launch(void* const* d_in, const int* in_sizes, int n_in,
                              void* d_out, int out_size) {
    (void)in_sizes; (void)n_in; (void)out_size;
    const float* x      = (const float*)d_in[0];
    const int*   qw     = (const int*)d_in[1];
    const float* scales = (const float*)d_in[2];
    const float* bias   = (const float*)d_in[3];
    const float* lA     = (const float*)d_in[4];
    const float* lB     = (const float*)d_in[5];
    float* out = (float*)d_out;

    cudaFuncSetAttribute(k_gemm, cudaFuncAttributeMaxDynamicSharedMemorySize, SMEM_BYTES);

    k_convert_x<<<4096, 256>>>(x);
    k_pad_x<<<(M_TOT * 8) / 256, 256>>>();
    k_convert_w<<<2048, 256>>>(qw, scales);
    k_tail_w<<<N_TOT, 64>>>(lB);
    k_xa<<<M_TOT / 32, 512>>>(x, lA);

    dim3 grid(N_TOT / CTA_N, M_TOT / CTA_M);
    k_gemm<<<grid, 512, SMEM_BYTES>>>(bias, out);
}